// round 1
// baseline (speedup 1.0000x reference)
#include <cuda_runtime.h>
#include <math.h>

#define HH 128
#define WW 128
#define HW (HH*WW)
#define CB 64
#define BB 16

// scratch (no cudaMalloc allowed)
__device__ float g_y[BB*576];                 // channel attention [b][c*9+k]
__device__ float g_weff[BB*CB*9*CB];          // modulated weights [b][cin][k][cout]
__device__ float g_hidden[BB*16*HW];          // SE conv1 output
__device__ float g_A[BB*HW];                  // spatial attention
__device__ float g_part[BB*8*64];             // pooling partials

// ---------------- stage 1: global average pool (partials) ----------------
__global__ void pool_partial(const float* __restrict__ x) {
    int b = blockIdx.x, s = blockIdx.y;               // s = spatial slice 0..7
    int w = threadIdx.x >> 5, lane = threadIdx.x & 31; // 16 warps
    #pragma unroll
    for (int j = 0; j < 4; j++) {
        int c = w * 4 + j;
        const float* p = x + ((size_t)b * CB + c) * HW + s * 2048;
        float sum = 0.f;
        #pragma unroll 8
        for (int i = lane; i < 2048; i += 32) sum += p[i];
        #pragma unroll
        for (int o = 16; o; o >>= 1) sum += __shfl_xor_sync(0xffffffffu, sum, o);
        if (lane == 0) g_part[(b * 8 + s) * 64 + c] = sum;
    }
}

// ---------------- stage 2: FC chain -> y[b][576] ----------------
__global__ void attn_fc(const float* __restrict__ fc_w1, const float* __restrict__ fc_w2) {
    int b = blockIdx.x, t = threadIdx.x;
    __shared__ float smean[64];
    __shared__ float sh[4];
    if (t < 64) {
        float s = 0.f;
        #pragma unroll
        for (int i = 0; i < 8; i++) s += g_part[(b * 8 + i) * 64 + t];
        smean[t] = s * (1.f / (float)HW);
    }
    __syncthreads();
    if (t < 4) {
        float s = 0.f;
        #pragma unroll
        for (int c = 0; c < 64; c++) s += smean[c] * fc_w1[t * 64 + c];
        sh[t] = fmaxf(s, 0.f);
    }
    __syncthreads();
    for (int j = t; j < 576; j += blockDim.x) {
        float s = 0.f;
        #pragma unroll
        for (int r = 0; r < 4; r++) s += sh[r] * fc_w2[j * 4 + r];
        g_y[b * 576 + j] = 1.f / (1.f + expf(-s));
    }
}

// ---------------- stage 3: modulated weights [b][c][k][o] ----------------
__global__ void build_weff(const float* __restrict__ weight) {
    int idx = blockIdx.x * blockDim.x + threadIdx.x;
    if (idx >= BB * CB * 9 * CB) return;
    int o = idx & 63;
    int k = (idx >> 6) % 9;
    int c = (idx / 576) & 63;
    int b = idx / (576 * 64);
    g_weff[idx] = weight[(o * 64 + c) * 9 + k] * g_y[b * 576 + c * 9 + k];
}

// ---------------- stage 4: SE conv1 (64 -> 16, relu) ----------------
__global__ void __launch_bounds__(256) se_conv1(const float* __restrict__ x,
                                                const float* __restrict__ se_w1) {
    __shared__ float sx[8][18][20];
    __shared__ float sw[8][9][16];
    int b = blockIdx.z;
    int x0 = blockIdx.x * 16, y0 = blockIdx.y * 16;
    int t = threadIdx.x;
    int cog = t >> 6, post = t & 63;
    int px = post & 15, pyg = post >> 4;
    float acc[4][4] = {};
    for (int cc = 0; cc < 8; cc++) {
        for (int idx = t; idx < 8 * 18 * 18; idx += 256) {
            int ci = idx / 324; int rem = idx - ci * 324;
            int r = rem / 18, cx = rem - r * 18;
            int gy = y0 + r - 1, gx = x0 + cx - 1;
            float v = 0.f;
            if ((unsigned)gy < HH && (unsigned)gx < WW)
                v = x[((size_t)(b * 64 + cc * 8 + ci)) * HW + gy * WW + gx];
            sx[ci][r][cx] = v;
        }
        for (int idx = t; idx < 8 * 9 * 16; idx += 256) {
            int co = idx & 15, k = (idx >> 4) % 9, ci = idx / 144;
            sw[ci][k][co] = se_w1[(co * 64 + cc * 8 + ci) * 9 + k];
        }
        __syncthreads();
        #pragma unroll
        for (int ci = 0; ci < 8; ci++)
        #pragma unroll
        for (int k = 0; k < 9; k++) {
            float wv[4], xv[4];
            #pragma unroll
            for (int j = 0; j < 4; j++) wv[j] = sw[ci][k][cog * 4 + j];
            #pragma unroll
            for (int i = 0; i < 4; i++) xv[i] = sx[ci][pyg * 4 + i + (k / 3)][px + (k % 3)];
            #pragma unroll
            for (int j = 0; j < 4; j++)
            #pragma unroll
            for (int i = 0; i < 4; i++) acc[j][i] += wv[j] * xv[i];
        }
        __syncthreads();
    }
    #pragma unroll
    for (int j = 0; j < 4; j++)
    #pragma unroll
    for (int i = 0; i < 4; i++) {
        int co = cog * 4 + j, y = y0 + pyg * 4 + i, xx = x0 + px;
        g_hidden[(b * 16 + co) * HW + y * WW + xx] = fmaxf(acc[j][i], 0.f);
    }
}

// ---------------- stage 5: SE conv2 (16 -> 1, sigmoid) ----------------
__global__ void __launch_bounds__(256) se_conv2(const float* __restrict__ se_w2) {
    __shared__ float sx[16][18][20];
    __shared__ float sw[144];
    int b = blockIdx.z;
    int x0 = blockIdx.x * 16, y0 = blockIdx.y * 16;
    int t = threadIdx.x;
    if (t < 144) sw[t] = se_w2[t];
    for (int idx = t; idx < 16 * 18 * 18; idx += 256) {
        int ci = idx / 324; int rem = idx - ci * 324;
        int r = rem / 18, cx = rem - r * 18;
        int gy = y0 + r - 1, gx = x0 + cx - 1;
        float v = 0.f;
        if ((unsigned)gy < HH && (unsigned)gx < WW)
            v = g_hidden[(b * 16 + ci) * HW + gy * WW + gx];
        sx[ci][r][cx] = v;
    }
    __syncthreads();
    int py = t >> 4, px = t & 15;
    float s = 0.f;
    #pragma unroll
    for (int ci = 0; ci < 16; ci++)
    #pragma unroll
    for (int k = 0; k < 9; k++)
        s += sw[ci * 9 + k] * sx[ci][py + k / 3][px + k % 3];
    g_A[b * HW + (y0 + py) * WW + x0 + px] = 1.f / (1.f + expf(-s));
}

// ---------------- stage 6: main modulated conv * A ----------------
__global__ void __launch_bounds__(256) main_conv(const float* __restrict__ x,
                                                 float* __restrict__ out) {
    __shared__ float sx[8][18][20];
    __shared__ float sw[8][9][32];
    int bz = blockIdx.z;
    int b = bz >> 1, half = bz & 1;
    int x0 = blockIdx.x * 16, y0 = blockIdx.y * 16;
    int t = threadIdx.x;
    int cog = t >> 6, post = t & 63;        // warp is co-uniform -> weight LDS broadcast
    int px = post & 15, pyg = post >> 4;    // conflict-free sx access pattern
    int co_base = half * 32;
    float acc[8][4] = {};
    for (int cc = 0; cc < 8; cc++) {
        for (int idx = t; idx < 8 * 18 * 18; idx += 256) {
            int ci = idx / 324; int rem = idx - ci * 324;
            int r = rem / 18, cx = rem - r * 18;
            int gy = y0 + r - 1, gx = x0 + cx - 1;
            float v = 0.f;
            if ((unsigned)gy < HH && (unsigned)gx < WW)
                v = x[((size_t)(b * 64 + cc * 8 + ci)) * HW + gy * WW + gx];
            sx[ci][r][cx] = v;
        }
        for (int idx = t; idx < 8 * 9 * 32; idx += 256) {
            int co = idx & 31, k = (idx >> 5) % 9, ci = idx / 288;
            sw[ci][k][co] = g_weff[((b * 64 + cc * 8 + ci) * 9 + k) * 64 + co_base + co];
        }
        __syncthreads();
        #pragma unroll
        for (int ci = 0; ci < 8; ci++)
        #pragma unroll
        for (int k = 0; k < 9; k++) {
            float wv[8], xv[4];
            #pragma unroll
            for (int j = 0; j < 8; j++) wv[j] = sw[ci][k][cog * 8 + j];
            #pragma unroll
            for (int i = 0; i < 4; i++) xv[i] = sx[ci][pyg * 4 + i + (k / 3)][px + (k % 3)];
            #pragma unroll
            for (int j = 0; j < 8; j++)
            #pragma unroll
            for (int i = 0; i < 4; i++) acc[j][i] += wv[j] * xv[i];
        }
        __syncthreads();
    }
    #pragma unroll
    for (int i = 0; i < 4; i++) {
        int y = y0 + pyg * 4 + i, xx = x0 + px;
        float av = g_A[b * HW + y * WW + xx];
        #pragma unroll
        for (int j = 0; j < 8; j++) {
            int co = co_base + cog * 8 + j;
            out[((size_t)(b * 64 + co)) * HW + y * WW + xx] = acc[j][i] * av;
        }
    }
}

extern "C" void kernel_launch(void* const* d_in, const int* in_sizes, int n_in,
                              void* d_out, int out_size) {
    const float* x      = (const float*)d_in[0];
    const float* weight = (const float*)d_in[1];
    const float* se_w1  = (const float*)d_in[2];
    const float* se_w2  = (const float*)d_in[3];
    const float* fc_w1  = (const float*)d_in[4];
    const float* fc_w2  = (const float*)d_in[5];
    float* out = (float*)d_out;

    pool_partial<<<dim3(BB, 8), 512>>>(x);
    attn_fc<<<BB, 576>>>(fc_w1, fc_w2);
    build_weff<<<(BB * CB * 9 * CB + 255) / 256, 256>>>(weight);
    se_conv1<<<dim3(8, 8, BB), 256>>>(x, se_w1);
    se_conv2<<<dim3(8, 8, BB), 256>>>(se_w2);
    main_conv<<<dim3(8, 8, BB * 2), 256>>>(x, out);
}

// round 3
// speedup vs baseline: 1.7995x; 1.7995x over previous
#include <cuda_runtime.h>
#include <cstdint>
#include <math.h>

#define HH 128
#define WW 128
#define HW (HH*WW)
#define CB 64
#define BB 16

// ---------------- scratch (no cudaMalloc allowed) ----------------
__device__ float g_y[BB*576];                 // channel attention [b][ci*9+k]
__device__ float g_weff2[BB*9*CB*CB];         // modulated weights [b][k][ci][co], tf32-rounded
__device__ float g_wse[9*CB*16];              // se_w1 reordered [k][ci][co16], tf32-rounded
__device__ float g_hidden[BB*16*HW];          // SE conv1 output
__device__ float g_A[BB*HW];                  // spatial attention
__device__ float g_part[BB*8*64];             // pooling partials

__device__ __forceinline__ float to_tf32(float x) {
    float r; asm("cvt.rna.tf32.f32 %0, %1;" : "=f"(r) : "f"(x)); return r;
}
__device__ __forceinline__ void mma8(float* d, const uint32_t* a, const uint32_t* b) {
    asm volatile(
        "mma.sync.aligned.m16n8k8.row.col.f32.tf32.tf32.f32 "
        "{%0,%1,%2,%3}, {%4,%5,%6,%7}, {%8,%9}, {%0,%1,%2,%3};\n"
        : "+f"(d[0]), "+f"(d[1]), "+f"(d[2]), "+f"(d[3])
        : "r"(a[0]), "r"(a[1]), "r"(a[2]), "r"(a[3]), "r"(b[0]), "r"(b[1]));
}

// ---------------- stage 1: global average pool (partials) ----------------
__global__ void pool_partial(const float* __restrict__ x) {
    int b = blockIdx.x, s = blockIdx.y;
    int w = threadIdx.x >> 5, lane = threadIdx.x & 31;
    #pragma unroll
    for (int j = 0; j < 4; j++) {
        int c = w * 4 + j;
        const float* p = x + ((size_t)b * CB + c) * HW + s * 2048;
        float sum = 0.f;
        #pragma unroll 8
        for (int i = lane; i < 2048; i += 32) sum += p[i];
        #pragma unroll
        for (int o = 16; o; o >>= 1) sum += __shfl_xor_sync(0xffffffffu, sum, o);
        if (lane == 0) g_part[(b * 8 + s) * 64 + c] = sum;
    }
}

// ---------------- stage 2: FC chain -> y ----------------
__global__ void attn_fc(const float* __restrict__ fc_w1, const float* __restrict__ fc_w2) {
    int b = blockIdx.x, t = threadIdx.x;
    __shared__ float smean[64];
    __shared__ float sh[4];
    if (t < 64) {
        float s = 0.f;
        #pragma unroll
        for (int i = 0; i < 8; i++) s += g_part[(b * 8 + i) * 64 + t];
        smean[t] = s * (1.f / (float)HW);
    }
    __syncthreads();
    if (t < 4) {
        float s = 0.f;
        #pragma unroll
        for (int c = 0; c < 64; c++) s += smean[c] * fc_w1[t * 64 + c];
        sh[t] = fmaxf(s, 0.f);
    }
    __syncthreads();
    for (int j = t; j < 576; j += blockDim.x) {
        float s = 0.f;
        #pragma unroll
        for (int r = 0; r < 4; r++) s += sh[r] * fc_w2[j * 4 + r];
        g_y[b * 576 + j] = 1.f / (1.f + expf(-s));
    }
}

// ---------------- stage 3a: modulated weights [b][k][ci][co], tf32 ----------------
__global__ void build_weff(const float* __restrict__ weight) {
    int idx = blockIdx.x * blockDim.x + threadIdx.x;
    if (idx >= BB * 9 * CB * CB) return;
    int co = idx & 63;
    int ci = (idx >> 6) & 63;
    int k  = (idx >> 12) % 9;
    int b  = idx / (9 * 64 * 64);
    g_weff2[idx] = to_tf32(weight[(co * 64 + ci) * 9 + k] * g_y[b * 576 + ci * 9 + k]);
}

// ---------------- stage 3b: se_w1 reorder [k][ci][co16], tf32 ----------------
__global__ void prep_wse(const float* __restrict__ se_w1) {
    int idx = blockIdx.x * blockDim.x + threadIdx.x;
    if (idx >= 9 * 64 * 16) return;
    int co = idx & 15;
    int ci = (idx >> 4) & 63;
    int k  = idx >> 10;
    g_wse[idx] = to_tf32(se_w1[(co * 64 + ci) * 9 + k]);
}

// ---------------- tf32 mma direct conv ----------------
// CTA: batch b (blockIdx.y), 4 image rows R0..R0+3 (R0 = blockIdx.x*4), all N = NT*8 co.
// 512 threads = 16 warps; warp w: row prow=w>>2, cols (w&3)*32 .. +31 (2 m-tiles of 16).
// K = 9 taps x 64 ci, processed as 4 chunks of 16 ci; taps realized as shifted smem reads.
// smem: sx[ci16][row6][col132] (stride 792 w, banks 24*tig+g: conflict-free)
//       sw[(k*16+ci)][72] (stride 72 w, banks 8*tig+g: conflict-free)
#define SX_WORDS (16*6*132)
#define SW_WORDS (9*16*72)
#define DYN_SMEM ((SX_WORDS + SW_WORDS) * 4)

template<int NT, int MODE>   // MODE 0: main conv (*A -> out), MODE 1: se conv1 (relu -> g_hidden)
__global__ void __launch_bounds__(512, 1) conv_mma(const float* __restrict__ x,
                                                   float* __restrict__ outp) {
    extern __shared__ uint32_t sm[];
    uint32_t* sxp = sm;
    uint32_t* swp = sm + SX_WORDS;
    const int tid = threadIdx.x, wid = tid >> 5, lane = tid & 31;
    const int g = lane >> 2, tig = lane & 3;
    const int b = blockIdx.y, R0 = blockIdx.x * 4;
    const int prow = wid >> 2, colbase = (wid & 3) * 32;

    float d[2][NT][4];
    #pragma unroll
    for (int mt = 0; mt < 2; mt++)
        #pragma unroll
        for (int nt = 0; nt < NT; nt++)
            #pragma unroll
            for (int r = 0; r < 4; r++) d[mt][nt][r] = 0.f;

    for (int cc = 0; cc < 4; ++cc) {
        const int ci0 = cc * 16;
        __syncthreads();
        // stage x tile: 16 ci x 6 rows x 132 cols, tf32-rounded
        for (int idx = tid; idx < 16 * 6 * 132; idx += 512) {
            int c = idx % 132; int rem = idx / 132; int r = rem % 6; int ci = rem / 6;
            int gy = R0 - 1 + r, gx = c - 1;
            float v = 0.f;
            if ((unsigned)gy < HH && (unsigned)gx < WW)
                v = x[((size_t)(b * 64 + ci0 + ci)) * HW + gy * WW + gx];
            sxp[ci * 792 + r * 132 + c] = __float_as_uint(to_tf32(v));
        }
        // stage weights: [k][ci16][co]
        for (int idx = tid; idx < 9 * 16 * NT * 8; idx += 512) {
            int co = idx % (NT * 8); int rem = idx / (NT * 8);
            int ci = rem % 16; int k = rem / 16;
            float v;
            if (MODE == 0) v = g_weff2[(((size_t)b * 9 + k) * 64 + ci0 + ci) * 64 + co];
            else           v = g_wse[(k * 64 + ci0 + ci) * 16 + co];
            swp[(k * 16 + ci) * 72 + co] = __float_as_uint(v);
        }
        __syncthreads();

        #pragma unroll
        for (int k = 0; k < 9; ++k) {
            const int dy = k / 3, dx = k % 3;
            #pragma unroll
            for (int s = 0; s < 2; ++s) {
                uint32_t bf[NT][2];
                #pragma unroll
                for (int nt = 0; nt < NT; ++nt) {
                    bf[nt][0] = swp[(k * 16 + s * 8 + tig) * 72 + nt * 8 + g];
                    bf[nt][1] = swp[(k * 16 + s * 8 + tig + 4) * 72 + nt * 8 + g];
                }
                #pragma unroll
                for (int mt = 0; mt < 2; ++mt) {
                    const int colb = colbase + mt * 16 + g + dx;
                    const int base0 = (s * 8 + tig) * 792 + (prow + dy) * 132 + colb;
                    const int base1 = (s * 8 + tig + 4) * 792 + (prow + dy) * 132 + colb;
                    uint32_t af[4];
                    af[0] = sxp[base0];        // row g,   kcol tig
                    af[1] = sxp[base0 + 8];    // row g+8, kcol tig
                    af[2] = sxp[base1];        // row g,   kcol tig+4
                    af[3] = sxp[base1 + 8];    // row g+8, kcol tig+4
                    #pragma unroll
                    for (int nt = 0; nt < NT; ++nt) mma8(d[mt][nt], af, bf[nt]);
                }
            }
        }
    }

    // epilogue
    const int grow = R0 + prow;
    #pragma unroll
    for (int mt = 0; mt < 2; ++mt) {
        const int col = colbase + mt * 16 + g;
        float av0 = 1.f, av1 = 1.f;
        if (MODE == 0) {
            av0 = g_A[b * HW + grow * WW + col];
            av1 = g_A[b * HW + grow * WW + col + 8];
        }
        #pragma unroll
        for (int nt = 0; nt < NT; ++nt) {
            const int co = nt * 8 + tig * 2;
            if (MODE == 0) {
                float* o0 = outp + ((size_t)(b * 64 + co)) * HW + grow * WW + col;
                float* o1 = o0 + HW;
                o0[0] = d[mt][nt][0] * av0;
                o1[0] = d[mt][nt][1] * av0;
                o0[8] = d[mt][nt][2] * av1;
                o1[8] = d[mt][nt][3] * av1;
            } else {
                float* o0 = g_hidden + ((size_t)(b * 16 + co)) * HW + grow * WW + col;
                float* o1 = o0 + HW;
                o0[0] = fmaxf(d[mt][nt][0], 0.f);
                o1[0] = fmaxf(d[mt][nt][1], 0.f);
                o0[8] = fmaxf(d[mt][nt][2], 0.f);
                o1[8] = fmaxf(d[mt][nt][3], 0.f);
            }
        }
    }
}

// ---------------- stage 5: SE conv2 (16 -> 1, sigmoid) ----------------
__global__ void __launch_bounds__(256) se_conv2(const float* __restrict__ se_w2) {
    __shared__ float sx[16][18][20];
    __shared__ float sw[144];
    int b = blockIdx.z;
    int x0 = blockIdx.x * 16, y0 = blockIdx.y * 16;
    int t = threadIdx.x;
    if (t < 144) sw[t] = se_w2[t];
    for (int idx = t; idx < 16 * 18 * 18; idx += 256) {
        int ci = idx / 324; int rem = idx - ci * 324;
        int r = rem / 18, cx = rem - r * 18;
        int gy = y0 + r - 1, gx = x0 + cx - 1;
        float v = 0.f;
        if ((unsigned)gy < HH && (unsigned)gx < WW)
            v = g_hidden[(b * 16 + ci) * HW + gy * WW + gx];
        sx[ci][r][cx] = v;
    }
    __syncthreads();
    int py = t >> 4, px = t & 15;
    float s = 0.f;
    #pragma unroll
    for (int ci = 0; ci < 16; ci++)
    #pragma unroll
    for (int k = 0; k < 9; k++)
        s += sw[ci * 9 + k] * sx[ci][py + k / 3][px + k % 3];
    g_A[b * HW + (y0 + py) * WW + x0 + px] = 1.f / (1.f + expf(-s));
}

extern "C" void kernel_launch(void* const* d_in, const int* in_sizes, int n_in,
                              void* d_out, int out_size) {
    const float* x      = (const float*)d_in[0];
    const float* weight = (const float*)d_in[1];
    const float* se_w1  = (const float*)d_in[2];
    const float* se_w2  = (const float*)d_in[3];
    const float* fc_w1  = (const float*)d_in[4];
    const float* fc_w2  = (const float*)d_in[5];
    float* out = (float*)d_out;

    cudaFuncSetAttribute(conv_mma<8,0>, cudaFuncAttributeMaxDynamicSharedMemorySize, DYN_SMEM);
    cudaFuncSetAttribute(conv_mma<2,1>, cudaFuncAttributeMaxDynamicSharedMemorySize, DYN_SMEM);

    pool_partial<<<dim3(BB, 8), 512>>>(x);
    attn_fc<<<BB, 576>>>(fc_w1, fc_w2);
    build_weff<<<(BB * 9 * CB * CB + 255) / 256, 256>>>(weight);
    prep_wse<<<(9 * CB * 16 + 255) / 256, 256>>>(se_w1);
    conv_mma<2,1><<<dim3(32, BB), 512, DYN_SMEM>>>(x, nullptr);   // SE conv1 -> g_hidden
    se_conv2<<<dim3(8, 8, BB), 256>>>(se_w2);                     // -> g_A
    conv_mma<8,0><<<dim3(32, BB), 512, DYN_SMEM>>>(x, out);       // main conv * A -> out
}

// round 4
// speedup vs baseline: 2.3208x; 1.2897x over previous
#include <cuda_runtime.h>
#include <cstdint>
#include <math.h>

#define HH 128
#define WW 128
#define HW (HH*WW)
#define CB 64
#define BB 16

// ---------------- scratch (no cudaMalloc allowed) ----------------
__device__ float g_y[BB*576];                 // channel attention [b][ci*9+k]
__device__ float g_weff2[BB*9*CB*CB];         // modulated weights [b][k][ci][co], tf32-rounded
__device__ float g_wse[9*CB*16];              // se_w1 reordered [k][ci][co16], tf32-rounded
__device__ float g_hidden[BB*16*HW];          // SE conv1 output
__device__ float g_A[BB*HW];                  // spatial attention
__device__ float g_mean[BB*CB];               // pooled means
__device__ float g_xc[(size_t)BB*CB*HW];      // tf32-rounded copy of x (64MB)

__device__ __forceinline__ float to_tf32(float x) {
    float r; asm("cvt.rna.tf32.f32 %0, %1;" : "=f"(r) : "f"(x)); return r;
}
__device__ __forceinline__ void mma8(float* d, const uint32_t* a, const uint32_t* b) {
    asm volatile(
        "mma.sync.aligned.m16n8k8.row.col.f32.tf32.tf32.f32 "
        "{%0,%1,%2,%3}, {%4,%5,%6,%7}, {%8,%9}, {%0,%1,%2,%3};\n"
        : "+f"(d[0]), "+f"(d[1]), "+f"(d[2]), "+f"(d[3])
        : "r"(a[0]), "r"(a[1]), "r"(a[2]), "r"(a[3]), "r"(b[0]), "r"(b[1]));
}
__device__ __forceinline__ void cp4z(uint32_t dst, const void* src, bool pred) {
    asm volatile("cp.async.ca.shared.global [%0], [%1], 4, %2;"
                 :: "r"(dst), "l"(src), "r"(pred ? 4u : 0u));
}
__device__ __forceinline__ void cp16(uint32_t dst, const void* src) {
    asm volatile("cp.async.cg.shared.global [%0], [%1], 16;" :: "r"(dst), "l"(src));
}
#define CP_COMMIT() asm volatile("cp.async.commit_group;" ::: "memory")

__device__ __forceinline__ uint32_t smem_u32(const void* p) {
    uint32_t a;
    asm("{ .reg .u64 t; cvta.to.shared.u64 t, %1; cvt.u32.u64 %0, t; }" : "=r"(a) : "l"(p));
    return a;
}

// ---------------- stage 1: tf32 pre-round + global average pool ----------------
__global__ void __launch_bounds__(256) convert_pool(const float* __restrict__ x) {
    int c = blockIdx.x, b = blockIdx.y, t = threadIdx.x;
    const float4* p = (const float4*)(x + ((size_t)(b * CB + c)) * HW);
    float4* o = (float4*)(g_xc + ((size_t)(b * CB + c)) * HW);
    float sum = 0.f;
    #pragma unroll 4
    for (int i = t; i < HW / 4; i += 256) {
        float4 v = p[i];
        sum += (v.x + v.y) + (v.z + v.w);
        v.x = to_tf32(v.x); v.y = to_tf32(v.y); v.z = to_tf32(v.z); v.w = to_tf32(v.w);
        o[i] = v;
    }
    #pragma unroll
    for (int off = 16; off; off >>= 1) sum += __shfl_xor_sync(0xffffffffu, sum, off);
    __shared__ float ws[8];
    if ((t & 31) == 0) ws[t >> 5] = sum;
    __syncthreads();
    if (t == 0) {
        float s = 0.f;
        #pragma unroll
        for (int i = 0; i < 8; i++) s += ws[i];
        g_mean[b * CB + c] = s * (1.f / (float)HW);
    }
}

// ---------------- stage 2: FC chain -> y ----------------
__global__ void attn_fc(const float* __restrict__ fc_w1, const float* __restrict__ fc_w2) {
    int b = blockIdx.x, t = threadIdx.x;
    __shared__ float smean[64];
    __shared__ float sh[4];
    if (t < 64) smean[t] = g_mean[b * 64 + t];
    __syncthreads();
    if (t < 4) {
        float s = 0.f;
        #pragma unroll
        for (int c = 0; c < 64; c++) s += smean[c] * fc_w1[t * 64 + c];
        sh[t] = fmaxf(s, 0.f);
    }
    __syncthreads();
    for (int j = t; j < 576; j += blockDim.x) {
        float s = 0.f;
        #pragma unroll
        for (int r = 0; r < 4; r++) s += sh[r] * fc_w2[j * 4 + r];
        g_y[b * 576 + j] = 1.f / (1.f + expf(-s));
    }
}

// ---------------- stage 3a: modulated weights [b][k][ci][co], tf32 ----------------
__global__ void build_weff(const float* __restrict__ weight) {
    int idx = blockIdx.x * blockDim.x + threadIdx.x;
    if (idx >= BB * 9 * CB * CB) return;
    int co = idx & 63;
    int ci = (idx >> 6) & 63;
    int k  = (idx >> 12) % 9;
    int b  = idx / (9 * 64 * 64);
    g_weff2[idx] = to_tf32(weight[(co * 64 + ci) * 9 + k] * g_y[b * 576 + ci * 9 + k]);
}

// ---------------- stage 3b: se_w1 reorder [k][ci][co16], tf32 ----------------
__global__ void prep_wse(const float* __restrict__ se_w1) {
    int idx = blockIdx.x * blockDim.x + threadIdx.x;
    if (idx >= 9 * 64 * 16) return;
    int co = idx & 15;
    int ci = (idx >> 4) & 63;
    int k  = idx >> 10;
    g_wse[idx] = to_tf32(se_w1[(co * 64 + ci) * 9 + k]);
}

// ---------------- tf32 mma direct conv, cp.async double-buffered ----------------
// CTA: batch b (blockIdx.y), 4 image rows R0..R0+3, all N = NT*8 co. 512 thr = 16 warps.
// K = 9 taps x 64 ci as 4 chunks of 16 ci; taps = shifted smem reads.
// Per buffer: sx[ci16][row6][col132] stride 792 (conflict-free), sw[(k*16+ci)][72].
#define SX_WORDS (16*6*132)
#define SW_WORDS (9*16*72)
#define BUF_WORDS (SX_WORDS + SW_WORDS)
#define DYN_SMEM (2 * BUF_WORDS * 4)

template<int NT, int MODE>   // MODE 0: main conv (*A -> out), MODE 1: se conv1 (relu -> g_hidden)
__global__ void __launch_bounds__(512, 1) conv_mma(float* __restrict__ outp) {
    extern __shared__ uint32_t sm[];
    const uint32_t smb = smem_u32(sm);
    const int tid = threadIdx.x, wid = tid >> 5, lane = tid & 31;
    const int g = lane >> 2, tig = lane & 3;
    const int b = blockIdx.y, R0 = blockIdx.x * 4;
    const int prow = wid >> 2, colbase = (wid & 3) * 32;

    // hoisted x-staging geometry: thread -> (ci_x, r_x, col quarter)
    const int sr = tid >> 2, q = tid & 3;
    const int ci_x = sr / 6, r_x = sr - ci_x * 6;
    const int gy = R0 - 1 + r_x;
    const bool xactive = sr < 96;
    const bool rowok = xactive && ((unsigned)gy < (unsigned)HH);
    const float* xrowb = g_xc + ((size_t)b * 64) * HW + (size_t)gy * WW - 1;
    const int c0 = q * 33;
    const uint32_t dxrow_off = (uint32_t)(ci_x * 792 + r_x * 132) * 4;

    auto stage = [&](int cc, int bufi) {
        const int ci0 = cc * 16;
        const uint32_t bufb = smb + (uint32_t)bufi * (BUF_WORDS * 4);
        if (xactive) {
            const float* srcrow = xrowb + (size_t)(ci0 + ci_x) * HW;
            const uint32_t drow = bufb + dxrow_off;
            #pragma unroll
            for (int j = 0; j < 33; j++) {
                int c = c0 + j;
                bool ok = rowok && ((unsigned)(c - 1) < (unsigned)WW);
                cp4z(drow + c * 4, srcrow + c, ok);
            }
        }
        // weights: 16B quads
        for (int idx = tid; idx < 9 * 16 * NT * 2; idx += 512) {
            int co4 = idx % (NT * 2);
            int rem = idx / (NT * 2);
            int ci = rem & 15, k = rem >> 4;
            const float* src;
            if (MODE == 0)
                src = g_weff2 + (((size_t)b * 9 + k) * 64 + ci0 + ci) * 64 + co4 * 4;
            else
                src = g_wse + ((size_t)k * 64 + ci0 + ci) * 16 + co4 * 4;
            uint32_t dst = bufb + (uint32_t)(SX_WORDS + (k * 16 + ci) * 72 + co4 * 4) * 4;
            cp16(dst, src);
        }
    };

    float d[2][NT][4];
    #pragma unroll
    for (int mt = 0; mt < 2; mt++)
        #pragma unroll
        for (int nt = 0; nt < NT; nt++)
            #pragma unroll
            for (int r = 0; r < 4; r++) d[mt][nt][r] = 0.f;

    stage(0, 0);
    CP_COMMIT();

    for (int cc = 0; cc < 4; ++cc) {
        if (cc < 3) {
            stage(cc + 1, (cc + 1) & 1);
            CP_COMMIT();
            asm volatile("cp.async.wait_group 1;" ::: "memory");
        } else {
            asm volatile("cp.async.wait_group 0;" ::: "memory");
        }
        __syncthreads();

        const uint32_t* sxp = sm + (cc & 1) * BUF_WORDS;
        const uint32_t* swp = sxp + SX_WORDS;

        #pragma unroll
        for (int k = 0; k < 9; ++k) {
            const int dy = k / 3, dx = k % 3;
            #pragma unroll
            for (int s = 0; s < 2; ++s) {
                uint32_t bf[NT][2];
                #pragma unroll
                for (int nt = 0; nt < NT; ++nt) {
                    bf[nt][0] = swp[(k * 16 + s * 8 + tig) * 72 + nt * 8 + g];
                    bf[nt][1] = swp[(k * 16 + s * 8 + tig + 4) * 72 + nt * 8 + g];
                }
                #pragma unroll
                for (int mt = 0; mt < 2; ++mt) {
                    const int colb = colbase + mt * 16 + g + dx;
                    const int base0 = (s * 8 + tig) * 792 + (prow + dy) * 132 + colb;
                    const int base1 = (s * 8 + tig + 4) * 792 + (prow + dy) * 132 + colb;
                    uint32_t af[4];
                    af[0] = sxp[base0];
                    af[1] = sxp[base0 + 8];
                    af[2] = sxp[base1];
                    af[3] = sxp[base1 + 8];
                    #pragma unroll
                    for (int nt = 0; nt < NT; ++nt) mma8(d[mt][nt], af, bf[nt]);
                }
            }
        }
        __syncthreads();
    }

    // epilogue
    const int grow = R0 + prow;
    #pragma unroll
    for (int mt = 0; mt < 2; ++mt) {
        const int col = colbase + mt * 16 + g;
        float av0 = 1.f, av1 = 1.f;
        if (MODE == 0) {
            av0 = g_A[b * HW + grow * WW + col];
            av1 = g_A[b * HW + grow * WW + col + 8];
        }
        #pragma unroll
        for (int nt = 0; nt < NT; ++nt) {
            const int co = nt * 8 + tig * 2;
            if (MODE == 0) {
                float* o0 = outp + ((size_t)(b * 64 + co)) * HW + grow * WW + col;
                float* o1 = o0 + HW;
                o0[0] = d[mt][nt][0] * av0;
                o1[0] = d[mt][nt][1] * av0;
                o0[8] = d[mt][nt][2] * av1;
                o1[8] = d[mt][nt][3] * av1;
            } else {
                float* o0 = g_hidden + ((size_t)(b * 16 + co)) * HW + grow * WW + col;
                float* o1 = o0 + HW;
                o0[0] = fmaxf(d[mt][nt][0], 0.f);
                o1[0] = fmaxf(d[mt][nt][1], 0.f);
                o0[8] = fmaxf(d[mt][nt][2], 0.f);
                o1[8] = fmaxf(d[mt][nt][3], 0.f);
            }
        }
    }
}

// ---------------- stage 5: SE conv2 (16 -> 1, sigmoid) ----------------
__global__ void __launch_bounds__(256) se_conv2(const float* __restrict__ se_w2) {
    __shared__ float sx[16][18][20];
    __shared__ float sw[144];
    int b = blockIdx.z;
    int x0 = blockIdx.x * 16, y0 = blockIdx.y * 16;
    int t = threadIdx.x;
    if (t < 144) sw[t] = se_w2[t];
    for (int idx = t; idx < 16 * 18 * 18; idx += 256) {
        int ci = idx / 324; int rem = idx - ci * 324;
        int r = rem / 18, cx = rem - r * 18;
        int gy = y0 + r - 1, gx = x0 + cx - 1;
        float v = 0.f;
        if ((unsigned)gy < HH && (unsigned)gx < WW)
            v = g_hidden[(b * 16 + ci) * HW + gy * WW + gx];
        sx[ci][r][cx] = v;
    }
    __syncthreads();
    int py = t >> 4, px = t & 15;
    float s = 0.f;
    #pragma unroll
    for (int ci = 0; ci < 16; ci++)
    #pragma unroll
    for (int k = 0; k < 9; k++)
        s += sw[ci * 9 + k] * sx[ci][py + k / 3][px + k % 3];
    g_A[b * HW + (y0 + py) * WW + x0 + px] = 1.f / (1.f + expf(-s));
}

extern "C" void kernel_launch(void* const* d_in, const int* in_sizes, int n_in,
                              void* d_out, int out_size) {
    const float* x      = (const float*)d_in[0];
    const float* weight = (const float*)d_in[1];
    const float* se_w1  = (const float*)d_in[2];
    const float* se_w2  = (const float*)d_in[3];
    const float* fc_w1  = (const float*)d_in[4];
    const float* fc_w2  = (const float*)d_in[5];
    float* out = (float*)d_out;

    cudaFuncSetAttribute(conv_mma<8,0>, cudaFuncAttributeMaxDynamicSharedMemorySize, DYN_SMEM);
    cudaFuncSetAttribute(conv_mma<2,1>, cudaFuncAttributeMaxDynamicSharedMemorySize, DYN_SMEM);

    convert_pool<<<dim3(CB, BB), 256>>>(x);                       // g_xc + g_mean
    attn_fc<<<BB, 576>>>(fc_w1, fc_w2);
    build_weff<<<(BB * 9 * CB * CB + 255) / 256, 256>>>(weight);
    prep_wse<<<(9 * CB * 16 + 255) / 256, 256>>>(se_w1);
    conv_mma<2,1><<<dim3(32, BB), 512, DYN_SMEM>>>(nullptr);      // SE conv1 -> g_hidden
    se_conv2<<<dim3(8, 8, BB), 256>>>(se_w2);                     // -> g_A
    conv_mma<8,0><<<dim3(32, BB), 512, DYN_SMEM>>>(out);          // main conv * A -> out
}